// round 6
// baseline (speedup 1.0000x reference)
#include <cuda_runtime.h>
#include <cuda_fp16.h>

// ============================================================================
// Fused window cross-attention (fp16 tensor cores, fp32 accumulation):
//   q = x1 @ q_w^T + q_b                       (fold in SCALE)
//   k,v = x2 @ kv_w^T + kv_b
//   S = q k^T + bias(table, rel_idx) + mask[b % 1024]
//   P = softmax(S); O = P v
//   y = O @ proj_w^T + proj_b
//
// One CTA (384 threads = 12 warps) handles 2 windows (M = 128 rows).
// All intermediates live in SMEM as fp16; tensor cores via mma.sync m16n8k16.
// ============================================================================

#define NUM_HEADS 6
#define HEAD_DIM  32
#define DIM       192
#define NWIN      64      // tokens per window
#define SCALE_F   0.17677669529663687f   // 32^-0.5

#define LDW   200         // padded row length (fp16 elems); 400B stride = 4 banks mod 32
#define LDWU  100         // row length in u32

// SMEM layout (bytes)
#define XB_OFF   0                       // 128*200*2 = 51200   (x staging; aliased as mask fp32 later)
#define QB_OFF   51200                   // q, later O
#define KB_OFF   102400
#define VB_OFF   153600
#define WT_OFF   204800                  // 48*200*2 = 19200 weight tile
#define TS_OFF   224000                  // 225*6*4  = 5400 bias table
#define SMEM_TOTAL 229400

// fp16 weight copies (converted once per launch by prep_kernel)
__device__ __align__(16) __half g_qw[192 * 192];
__device__ __align__(16) __half g_kvw[384 * 192];
__device__ __align__(16) __half g_pjw[192 * 192];

__global__ void prep_kernel(const float* __restrict__ qw,
                            const float* __restrict__ kvw,
                            const float* __restrict__ pw) {
    int i = blockIdx.x * blockDim.x + threadIdx.x;
    if (i < 192 * 192) g_qw[i]  = __float2half_rn(qw[i]);
    if (i < 384 * 192) g_kvw[i] = __float2half_rn(kvw[i]);
    if (i < 192 * 192) g_pjw[i] = __float2half_rn(pw[i]);
}

static __device__ __forceinline__ unsigned sm_u32(const void* p) {
    return (unsigned)__cvta_generic_to_shared(p);
}

#define LDM_X4(R, ADDR) \
    asm volatile("ldmatrix.sync.aligned.m8n8.x4.shared.b16 {%0,%1,%2,%3}, [%4];" \
                 : "=r"((R)[0]), "=r"((R)[1]), "=r"((R)[2]), "=r"((R)[3]) : "r"(ADDR))
#define LDM_X2(R, ADDR) \
    asm volatile("ldmatrix.sync.aligned.m8n8.x2.shared.b16 {%0,%1}, [%2];" \
                 : "=r"((R)[0]), "=r"((R)[1]) : "r"(ADDR))
#define LDM_X2T(R, ADDR) \
    asm volatile("ldmatrix.sync.aligned.m8n8.x2.trans.shared.b16 {%0,%1}, [%2];" \
                 : "=r"((R)[0]), "=r"((R)[1]) : "r"(ADDR))
#define MMA_F16(D, A, B) \
    asm volatile("mma.sync.aligned.m16n8k16.row.col.f32.f16.f16.f32 " \
                 "{%0,%1,%2,%3},{%4,%5,%6,%7},{%8,%9},{%0,%1,%2,%3};" \
                 : "+f"((D)[0]), "+f"((D)[1]), "+f"((D)[2]), "+f"((D)[3]) \
                 : "r"((A)[0]), "r"((A)[1]), "r"((A)[2]), "r"((A)[3]), \
                   "r"((B)[0]), "r"((B)[1]))

static __device__ __forceinline__ unsigned pack_half2(float a, float b) {
    __half2 h = __floats2half2_rn(a, b);
    return *(unsigned*)&h;
}

// One warp computes a 32(M) x 16(N) output tile over K=192.
// X: fp16 SMEM, rows = M (row stride LDW). WT: fp16 SMEM, rows = out-channels.
static __device__ __forceinline__ void mma_block48(unsigned xa_u, unsigned wt_u,
                                                   int mrow0, int ncol0, int lane,
                                                   float acc[2][2][4]) {
#pragma unroll
    for (int a = 0; a < 2; a++)
#pragma unroll
        for (int b = 0; b < 2; b++)
#pragma unroll
            for (int r = 0; r < 4; r++) acc[a][b][r] = 0.f;

    const unsigned aAddr = xa_u + (((mrow0 + (lane & 15)) * LDW + ((lane >> 4) * 8)) * 2);
    const unsigned bAddr = wt_u + (((ncol0 + (lane & 7)) * LDW + (((lane >> 3) & 1) * 8)) * 2);

#pragma unroll
    for (int k0 = 0; k0 < 192; k0 += 16) {
        unsigned A0[4], A1[4], B0[2], B1[2];
        LDM_X4(A0, aAddr + k0 * 2);
        LDM_X4(A1, aAddr + k0 * 2 + 16 * LDW * 2);
        LDM_X2(B0, bAddr + k0 * 2);
        LDM_X2(B1, bAddr + k0 * 2 + 8 * LDW * 2);
        MMA_F16(acc[0][0], A0, B0);
        MMA_F16(acc[0][1], A0, B1);
        MMA_F16(acc[1][0], A1, B0);
        MMA_F16(acc[1][1], A1, B1);
    }
}

__global__ void __launch_bounds__(384, 1)
wca_kernel(const float* __restrict__ x1, const float* __restrict__ x2,
           const float* __restrict__ mask,
           const float* __restrict__ q_b, const float* __restrict__ kv_b,
           const float* __restrict__ proj_b, const float* __restrict__ table,
           float* __restrict__ out) {
    extern __shared__ __align__(16) unsigned char smem[];
    __half* XB = (__half*)(smem + XB_OFF);
    __half* QB = (__half*)(smem + QB_OFF);
    __half* KB = (__half*)(smem + KB_OFF);
    __half* VB = (__half*)(smem + VB_OFF);
    __half* WT = (__half*)(smem + WT_OFF);
    float* TS = (float*)(smem + TS_OFF);
    float* MS = (float*)(smem + XB_OFF);   // mask staging, aliases XB (dead by then)

    const int tid = threadIdx.x;
    const int lane = tid & 31;
    const int wid = tid >> 5;
    const int b0 = blockIdx.x * 2;         // first of 2 windows

    const unsigned xb_u = sm_u32(XB), qbuf_u = sm_u32(QB);
    const unsigned kb_u = sm_u32(KB), vb_u = sm_u32(VB), wt_u = sm_u32(WT);

    // warp tiling for the 128x48 GEMM chunks: 4 (M) x 3 (N)
    const int mi = wid / 3;   // 0..3 -> 32 rows each
    const int ni = wid % 3;   // 0..2 -> 16 cols each

    // ---- bias table -> SMEM (once) ----
    for (int i = tid; i < 225 * 6; i += 384) TS[i] = table[i];

    // ---- load x1 (128 x 192 fp32 -> fp16 SMEM) ----
    {
        const float4* src = (const float4*)(x1 + (size_t)b0 * NWIN * DIM);
        unsigned* xbu = (unsigned*)XB;
        for (int i = tid; i < 128 * 48; i += 384) {
            int r = i / 48, c = i % 48;
            float4 v = src[r * 48 + c];
            xbu[r * LDWU + c * 2]     = pack_half2(v.x, v.y);
            xbu[r * LDWU + c * 2 + 1] = pack_half2(v.z, v.w);
        }
    }
    __syncthreads();

    // ======================= Q projection =======================
    for (int ch = 0; ch < 4; ch++) {
        const int c0 = ch * 48;
        {
            const unsigned* gw = (const unsigned*)(g_qw + c0 * 192);
            unsigned* wtu = (unsigned*)WT;
            for (int i = tid; i < 48 * 96; i += 384)
                wtu[(i / 96) * LDWU + (i % 96)] = gw[i];
        }
        __syncthreads();
        float acc[2][2][4];
        mma_block48(xb_u, wt_u, mi * 32, ni * 16, lane, acc);
        __syncthreads();
#pragma unroll
        for (int mt = 0; mt < 2; mt++)
#pragma unroll
            for (int nt = 0; nt < 2; nt++) {
                int row = mi * 32 + mt * 16 + (lane >> 2);
                int col = c0 + ni * 16 + nt * 8 + (lane & 3) * 2;
                float bb0 = q_b[col], bb1 = q_b[col + 1];
                QB[row * LDW + col]           = __float2half_rn((acc[mt][nt][0] + bb0) * SCALE_F);
                QB[row * LDW + col + 1]       = __float2half_rn((acc[mt][nt][1] + bb1) * SCALE_F);
                QB[(row + 8) * LDW + col]     = __float2half_rn((acc[mt][nt][2] + bb0) * SCALE_F);
                QB[(row + 8) * LDW + col + 1] = __float2half_rn((acc[mt][nt][3] + bb1) * SCALE_F);
            }
    }

    // ---- load x2 (overwrite XB) ----
    {
        const float4* src = (const float4*)(x2 + (size_t)b0 * NWIN * DIM);
        unsigned* xbu = (unsigned*)XB;
        for (int i = tid; i < 128 * 48; i += 384) {
            int r = i / 48, c = i % 48;
            float4 v = src[r * 48 + c];
            xbu[r * LDWU + c * 2]     = pack_half2(v.x, v.y);
            xbu[r * LDWU + c * 2 + 1] = pack_half2(v.z, v.w);
        }
    }
    __syncthreads();

    // ======================= K / V projection =======================
    for (int ch = 0; ch < 8; ch++) {
        const int c0 = ch * 48;
        {
            const unsigned* gw = (const unsigned*)(g_kvw + c0 * 192);
            unsigned* wtu = (unsigned*)WT;
            for (int i = tid; i < 48 * 96; i += 384)
                wtu[(i / 96) * LDWU + (i % 96)] = gw[i];
        }
        __syncthreads();
        float acc[2][2][4];
        mma_block48(xb_u, wt_u, mi * 32, ni * 16, lane, acc);
        __syncthreads();
        __half* OB = (c0 < 192) ? KB : VB;
        const int cshift = (c0 < 192) ? 0 : 192;
#pragma unroll
        for (int mt = 0; mt < 2; mt++)
#pragma unroll
            for (int nt = 0; nt < 2; nt++) {
                int row = mi * 32 + mt * 16 + (lane >> 2);
                int cg = c0 + ni * 16 + nt * 8 + (lane & 3) * 2;
                float bb0 = kv_b[cg], bb1 = kv_b[cg + 1];
                int col = cg - cshift;
                OB[row * LDW + col]           = __float2half_rn(acc[mt][nt][0] + bb0);
                OB[row * LDW + col + 1]       = __float2half_rn(acc[mt][nt][1] + bb1);
                OB[(row + 8) * LDW + col]     = __float2half_rn(acc[mt][nt][2] + bb0);
                OB[(row + 8) * LDW + col + 1] = __float2half_rn(acc[mt][nt][3] + bb1);
            }
    }

    // ======================= Attention =======================
    // 12 warps = (6 heads) x (2 row-halves) per window; window loop serialized.
    const int h = wid >> 1;
    const int half = wid & 1;
    const int rq = lane >> 2;            // 0..7
    const int cq = (lane & 3) * 2;       // 0,2,4,6

    for (int w = 0; w < 2; w++) {
        __syncthreads();   // prior readers of MS / writers of KB,VB,QB done
        {
            const float* mw = mask + (size_t)((b0 + w) & 1023) * (NWIN * NWIN);
            for (int i = tid; i < NWIN * NWIN; i += 384) MS[i] = mw[i];
        }
        __syncthreads();

        const int nbase = half * 32;          // within-window row base
        const int grow0 = w * 64 + nbase;     // row base in SMEM buffers

        // Q fragments: 32 rows x 32 head-dims
        unsigned qa[2][2][4];
        {
            unsigned base = qbuf_u + (((grow0 + (lane & 15)) * LDW) + h * 32 + ((lane >> 4) * 8)) * 2;
            LDM_X4(qa[0][0], base);
            LDM_X4(qa[0][1], base + 16 * 2);
            LDM_X4(qa[1][0], base + 16 * LDW * 2);
            LDM_X4(qa[1][1], base + (16 * LDW + 16) * 2);
        }

        // S = Q K^T  (32 x 64)
        float s[2][8][4];
#pragma unroll
        for (int a = 0; a < 2; a++)
#pragma unroll
            for (int b = 0; b < 8; b++)
#pragma unroll
                for (int r = 0; r < 4; r++) s[a][b][r] = 0.f;
        {
            unsigned kbase = kb_u + (((w * 64 + (lane & 7)) * LDW) + h * 32 + (((lane >> 3) & 1) * 8)) * 2;
#pragma unroll
            for (int nt = 0; nt < 8; nt++) {
                unsigned B0[2], B1[2];
                LDM_X2(B0, kbase + nt * 8 * LDW * 2);
                LDM_X2(B1, kbase + nt * 8 * LDW * 2 + 16 * 2);
                MMA_F16(s[0][nt], qa[0][0], B0);
                MMA_F16(s[0][nt], qa[0][1], B1);
                MMA_F16(s[1][nt], qa[1][0], B0);
                MMA_F16(s[1][nt], qa[1][1], B1);
            }
        }

        // + relative-position bias (arithmetic index into table) + mask
#pragma unroll
        for (int mt = 0; mt < 2; mt++)
#pragma unroll
            for (int hi = 0; hi < 2; hi++) {
                int n = nbase + mt * 16 + hi * 8 + rq;
                int pr = n >> 3, pc = n & 7;
#pragma unroll
                for (int nt = 0; nt < 8; nt++)
#pragma unroll
                    for (int e = 0; e < 2; e++) {
                        int m = nt * 8 + cq + e;
                        int idx = (pr - (m >> 3) + 7) * 15 + (pc - (m & 7) + 7);
                        s[mt][nt][hi * 2 + e] += TS[idx * 6 + h] + MS[n * 64 + m];
                    }
            }

        // softmax per row (row spread over 4 lanes: quad shuffles)
#pragma unroll
        for (int mt = 0; mt < 2; mt++)
#pragma unroll
            for (int hi = 0; hi < 2; hi++) {
                float mx = -1e30f;
#pragma unroll
                for (int nt = 0; nt < 8; nt++)
                    mx = fmaxf(mx, fmaxf(s[mt][nt][hi * 2], s[mt][nt][hi * 2 + 1]));
                mx = fmaxf(mx, __shfl_xor_sync(0xffffffffu, mx, 1));
                mx = fmaxf(mx, __shfl_xor_sync(0xffffffffu, mx, 2));
                float sum = 0.f;
#pragma unroll
                for (int nt = 0; nt < 8; nt++) {
                    float p0 = __expf(s[mt][nt][hi * 2] - mx);
                    float p1 = __expf(s[mt][nt][hi * 2 + 1] - mx);
                    s[mt][nt][hi * 2] = p0;
                    s[mt][nt][hi * 2 + 1] = p1;
                    sum += p0 + p1;
                }
                sum += __shfl_xor_sync(0xffffffffu, sum, 1);
                sum += __shfl_xor_sync(0xffffffffu, sum, 2);
                float inv = 1.f / sum;
#pragma unroll
                for (int nt = 0; nt < 8; nt++) {
                    s[mt][nt][hi * 2] *= inv;
                    s[mt][nt][hi * 2 + 1] *= inv;
                }
            }

        // pack P to fp16x2 (accumulator layout == next mma's A layout)
        unsigned pk[2][8][2];
#pragma unroll
        for (int mt = 0; mt < 2; mt++)
#pragma unroll
            for (int nt = 0; nt < 8; nt++) {
                pk[mt][nt][0] = pack_half2(s[mt][nt][0], s[mt][nt][1]);
                pk[mt][nt][1] = pack_half2(s[mt][nt][2], s[mt][nt][3]);
            }

        // O = P V  (32 x 32)
        float o[2][4][4];
#pragma unroll
        for (int a = 0; a < 2; a++)
#pragma unroll
            for (int b = 0; b < 4; b++)
#pragma unroll
                for (int r = 0; r < 4; r++) o[a][b][r] = 0.f;
#pragma unroll
        for (int j = 0; j < 4; j++) {
            unsigned vb[4][2];
            unsigned vbase = vb_u + (((w * 64 + j * 16 + (lane & 15)) * LDW) + h * 32) * 2;
#pragma unroll
            for (int dt = 0; dt < 4; dt++) LDM_X2T(vb[dt], vbase + dt * 8 * 2);
#pragma unroll
            for (int mt = 0; mt < 2; mt++) {
                unsigned pa[4] = { pk[mt][2 * j][0], pk[mt][2 * j][1],
                                   pk[mt][2 * j + 1][0], pk[mt][2 * j + 1][1] };
#pragma unroll
                for (int dt = 0; dt < 4; dt++) MMA_F16(o[mt][dt], pa, vb[dt]);
            }
        }

        // write O over this subtask's Q slice (same rows, same head cols)
#pragma unroll
        for (int mt = 0; mt < 2; mt++)
#pragma unroll
            for (int dt = 0; dt < 4; dt++) {
                int row = grow0 + mt * 16 + rq;
                int col = h * 32 + dt * 8 + cq;
                QB[row * LDW + col]           = __float2half_rn(o[mt][dt][0]);
                QB[row * LDW + col + 1]       = __float2half_rn(o[mt][dt][1]);
                QB[(row + 8) * LDW + col]     = __float2half_rn(o[mt][dt][2]);
                QB[(row + 8) * LDW + col + 1] = __float2half_rn(o[mt][dt][3]);
            }
    }
    __syncthreads();   // all O writes visible before projection reads QB

    // ======================= Output projection =======================
    for (int ch = 0; ch < 4; ch++) {
        const int c0 = ch * 48;
        {
            const unsigned* gw = (const unsigned*)(g_pjw + c0 * 192);
            unsigned* wtu = (unsigned*)WT;
            for (int i = tid; i < 48 * 96; i += 384)
                wtu[(i / 96) * LDWU + (i % 96)] = gw[i];
        }
        __syncthreads();
        float acc[2][2][4];
        mma_block48(qbuf_u, wt_u, mi * 32, ni * 16, lane, acc);
        __syncthreads();
#pragma unroll
        for (int mt = 0; mt < 2; mt++)
#pragma unroll
            for (int nt = 0; nt < 2; nt++) {
                int row = mi * 32 + mt * 16 + (lane >> 2);
                int col = c0 + ni * 16 + nt * 8 + (lane & 3) * 2;
                float bb0 = proj_b[col], bb1 = proj_b[col + 1];
                float* o0 = out + ((size_t)(b0 * NWIN + row)) * DIM + col;
                float* o1 = out + ((size_t)(b0 * NWIN + row + 8)) * DIM + col;
                o0[0] = acc[mt][nt][0] + bb0;
                o0[1] = acc[mt][nt][1] + bb1;
                o1[0] = acc[mt][nt][2] + bb0;
                o1[1] = acc[mt][nt][3] + bb1;
            }
    }
}

extern "C" void kernel_launch(void* const* d_in, const int* in_sizes, int n_in,
                              void* d_out, int out_size) {
    const float* x1     = (const float*)d_in[0];
    const float* x2     = (const float*)d_in[1];
    const float* mask   = (const float*)d_in[2];
    const float* q_w    = (const float*)d_in[3];
    const float* q_b    = (const float*)d_in[4];
    const float* kv_w   = (const float*)d_in[5];
    const float* kv_b   = (const float*)d_in[6];
    const float* proj_w = (const float*)d_in[7];
    const float* proj_b = (const float*)d_in[8];
    const float* table  = (const float*)d_in[9];

    prep_kernel<<<288, 256>>>(q_w, kv_w, proj_w);

    cudaFuncSetAttribute(wca_kernel, cudaFuncAttributeMaxDynamicSharedMemorySize, SMEM_TOTAL);
    wca_kernel<<<4096, 384, SMEM_TOTAL>>>(x1, x2, mask, q_b, kv_b, proj_b, table,
                                          (float*)d_out);
}

// round 8
// speedup vs baseline: 2.1285x; 2.1285x over previous
#include <cuda_runtime.h>
#include <cuda_fp16.h>

// ============================================================================
// Fused window cross-attention (fp16 mma.sync, fp32 accum), v2:
//  - 1 window per CTA (grid 8192), 384 threads, smem 102.4KB -> 2 CTAs/SM
//  - weights pre-packed into mma B-fragment order -> B loaded by LDG.128 from
//    L2 (no smem staging, no B ldmatrix), 6 barriers total
// ============================================================================

#define NUM_HEADS 6
#define HEAD_DIM  32
#define DIM       192
#define NWIN      64
#define SCALE_F   0.17677669529663687f   // 32^-0.5
#define KSTEPS    12                     // 192 / 16

#define LDW   200     // padded row length (fp16); 400B stride -> conflict-free ldmatrix
#define LDWU  100

// SMEM layout (bytes): 4 buffers of 64*200*2 = 25600
#define XB_OFF   0          // x staging; later mask (fp32, 16384B) + table (fp32, 5400B @ +16384)
#define QB_OFF   25600      // q, later O
#define KB_OFF   51200
#define VB_OFF   76800
#define SMEM_TOTAL 102400

// Weights in mma-B-fragment order: frag index ((t*12 + s)*32 + lane), uint4 each.
//   n  = t*16 + lane/4,  k0 = s*16 + (lane%4)*2
//   .x = half2(W[n][k0],   W[n][k0+1])   .y = half2(W[n][k0+8], W[n][k0+9])
//   .z/.w = same with n+8
__device__ __align__(16) uint4 g_bq [12 * KSTEPS * 32];
__device__ __align__(16) uint4 g_bkv[24 * KSTEPS * 32];
__device__ __align__(16) uint4 g_bp [12 * KSTEPS * 32];

static __device__ __forceinline__ unsigned pack_half2(float a, float b) {
    __half2 h = __floats2half2_rn(a, b);
    return *(unsigned*)&h;
}

static __device__ __forceinline__ uint4 make_frag(const float* __restrict__ W,
                                                  int t, int s, int l) {
    int n  = t * 16 + (l >> 2);
    int k0 = s * 16 + (l & 3) * 2;
    const float* r0 = W + (size_t)n * DIM;
    const float* r1 = W + (size_t)(n + 8) * DIM;
    uint4 u;
    u.x = pack_half2(r0[k0],     r0[k0 + 1]);
    u.y = pack_half2(r0[k0 + 8], r0[k0 + 9]);
    u.z = pack_half2(r1[k0],     r1[k0 + 1]);
    u.w = pack_half2(r1[k0 + 8], r1[k0 + 9]);
    return u;
}

__global__ void prep_kernel(const float* __restrict__ qw,
                            const float* __restrict__ kvw,
                            const float* __restrict__ pw) {
    int i = blockIdx.x * blockDim.x + threadIdx.x;   // 18432 total
    if (i < 4608) {
        int t = i / 384, r = i % 384, s = r / 32, l = r % 32;
        g_bq[i] = make_frag(qw, t, s, l);
    } else if (i < 13824) {
        int j = i - 4608;
        int t = j / 384, r = j % 384, s = r / 32, l = r % 32;
        g_bkv[j] = make_frag(kvw, t, s, l);
    } else if (i < 18432) {
        int j = i - 13824;
        int t = j / 384, r = j % 384, s = r / 32, l = r % 32;
        g_bp[j] = make_frag(pw, t, s, l);
    }
}

static __device__ __forceinline__ unsigned sm_u32(const void* p) {
    return (unsigned)__cvta_generic_to_shared(p);
}

#define LDM_X4(R, ADDR) \
    asm volatile("ldmatrix.sync.aligned.m8n8.x4.shared.b16 {%0,%1,%2,%3}, [%4];" \
                 : "=r"((R)[0]), "=r"((R)[1]), "=r"((R)[2]), "=r"((R)[3]) : "r"(ADDR))
#define LDM_X2(R, ADDR) \
    asm volatile("ldmatrix.sync.aligned.m8n8.x2.shared.b16 {%0,%1}, [%2];" \
                 : "=r"((R)[0]), "=r"((R)[1]) : "r"(ADDR))
#define LDM_X2T(R, ADDR) \
    asm volatile("ldmatrix.sync.aligned.m8n8.x2.trans.shared.b16 {%0,%1}, [%2];" \
                 : "=r"((R)[0]), "=r"((R)[1]) : "r"(ADDR))
#define MMA_F16(D, A, B) \
    asm volatile("mma.sync.aligned.m16n8k16.row.col.f32.f16.f16.f32 " \
                 "{%0,%1,%2,%3},{%4,%5,%6,%7},{%8,%9},{%0,%1,%2,%3};" \
                 : "+f"((D)[0]), "+f"((D)[1]), "+f"((D)[2]), "+f"((D)[3]) \
                 : "r"((A)[0]), "r"((A)[1]), "r"((A)[2]), "r"((A)[3]), \
                   "r"((B)[0]), "r"((B)[1]))

// 64(M) x 16(N) x 192(K) warp GEMM: A fp16 in smem (row stride LDW),
// B fragments streamed from gmem (one uint4 / k-step / lane).
static __device__ __forceinline__ void gemm64x16(unsigned a_u,
                                                 const uint4* __restrict__ bt,
                                                 int lane, float acc[4][2][4]) {
#pragma unroll
    for (int mt = 0; mt < 4; mt++)
#pragma unroll
        for (int n8 = 0; n8 < 2; n8++)
#pragma unroll
            for (int r = 0; r < 4; r++) acc[mt][n8][r] = 0.f;

    const unsigned aAddr = a_u + (((lane & 15) * LDW + (lane >> 4) * 8) * 2);
    uint4 bc = bt[lane];
#pragma unroll
    for (int s = 0; s < KSTEPS; s++) {
        uint4 bn = (s + 1 < KSTEPS) ? bt[(s + 1) * 32 + lane] : bc;
        unsigned B0[2] = { bc.x, bc.y };
        unsigned B1[2] = { bc.z, bc.w };
#pragma unroll
        for (int mt = 0; mt < 4; mt++) {
            unsigned A[4];
            LDM_X4(A, aAddr + (s * 16) * 2 + mt * (16 * LDW * 2));
            MMA_F16(acc[mt][0], A, B0);
            MMA_F16(acc[mt][1], A, B1);
        }
        bc = bn;
    }
}

__global__ void __launch_bounds__(384, 2)
wca_kernel(const float* __restrict__ x1, const float* __restrict__ x2,
           const float* __restrict__ mask,
           const float* __restrict__ q_b, const float* __restrict__ kv_b,
           const float* __restrict__ proj_b, const float* __restrict__ table,
           float* __restrict__ out) {
    extern __shared__ __align__(16) unsigned char smem[];
    __half* XB = (__half*)(smem + XB_OFF);
    __half* QB = (__half*)(smem + QB_OFF);
    __half* KB = (__half*)(smem + KB_OFF);
    __half* VB = (__half*)(smem + VB_OFF);
    float*  MS = (float*)(smem + XB_OFF);            // 64*64*4 = 16384, aliases XB
    float*  TS = (float*)(smem + XB_OFF + 16384);    // 225*6*4 = 5400,  aliases XB

    const int tid  = threadIdx.x;
    const int lane = tid & 31;
    const int wid  = tid >> 5;
    const int b    = blockIdx.x;                     // one window

    const unsigned xb_u = sm_u32(XB), qb_u = sm_u32(QB);
    const unsigned kb_u = sm_u32(KB), vb_u = sm_u32(VB);
    const int rq = lane >> 2;            // 0..7
    const int cq = (lane & 3) * 2;       // 0,2,4,6

    // ---- load x1 (64 x 192 fp32 -> fp16 smem) ----
    {
        const float4* src = (const float4*)(x1 + (size_t)b * NWIN * DIM);
        unsigned* xbu = (unsigned*)XB;
#pragma unroll
        for (int i = tid; i < 64 * 48; i += 384) {
            int r = i / 48, c = i % 48;
            float4 v = src[i];
            xbu[r * LDWU + c * 2]     = pack_half2(v.x, v.y);
            xbu[r * LDWU + c * 2 + 1] = pack_half2(v.z, v.w);
        }
    }
    __syncthreads();

    // ======================= Q projection (1 round) =======================
    {
        float acc[4][2][4];
        gemm64x16(xb_u, g_bq + wid * (KSTEPS * 32), lane, acc);
        int colb = wid * 16;
#pragma unroll
        for (int mt = 0; mt < 4; mt++)
#pragma unroll
            for (int n8 = 0; n8 < 2; n8++) {
                int row = mt * 16 + rq;
                int col = colb + n8 * 8 + cq;
                float bb0 = q_b[col], bb1 = q_b[col + 1];
                QB[row * LDW + col]           = __float2half_rn((acc[mt][n8][0] + bb0) * SCALE_F);
                QB[row * LDW + col + 1]       = __float2half_rn((acc[mt][n8][1] + bb1) * SCALE_F);
                QB[(row + 8) * LDW + col]     = __float2half_rn((acc[mt][n8][2] + bb0) * SCALE_F);
                QB[(row + 8) * LDW + col + 1] = __float2half_rn((acc[mt][n8][3] + bb1) * SCALE_F);
            }
    }
    __syncthreads();   // XB (x1) fully consumed

    // ---- load x2 into XB ----
    {
        const float4* src = (const float4*)(x2 + (size_t)b * NWIN * DIM);
        unsigned* xbu = (unsigned*)XB;
#pragma unroll
        for (int i = tid; i < 64 * 48; i += 384) {
            int r = i / 48, c = i % 48;
            float4 v = src[i];
            xbu[r * LDWU + c * 2]     = pack_half2(v.x, v.y);
            xbu[r * LDWU + c * 2 + 1] = pack_half2(v.z, v.w);
        }
    }
    __syncthreads();

    // ======================= K / V projection (2 iterations) ===============
#pragma unroll
    for (int it = 0; it < 2; it++) {
        int t = wid + it * 12;            // 0..11 -> K, 12..23 -> V
        float acc[4][2][4];
        gemm64x16(xb_u, g_bkv + t * (KSTEPS * 32), lane, acc);
        __half* OB = it ? VB : KB;
        int cg = t * 16;                  // global output channel base
        int colb = (it ? cg - 192 : cg);
#pragma unroll
        for (int mt = 0; mt < 4; mt++)
#pragma unroll
            for (int n8 = 0; n8 < 2; n8++) {
                int row = mt * 16 + rq;
                int gcol = cg + n8 * 8 + cq;
                int col  = colb + n8 * 8 + cq;
                float bb0 = kv_b[gcol], bb1 = kv_b[gcol + 1];
                OB[row * LDW + col]           = __float2half_rn(acc[mt][n8][0] + bb0);
                OB[row * LDW + col + 1]       = __float2half_rn(acc[mt][n8][1] + bb1);
                OB[(row + 8) * LDW + col]     = __float2half_rn(acc[mt][n8][2] + bb0);
                OB[(row + 8) * LDW + col + 1] = __float2half_rn(acc[mt][n8][3] + bb1);
            }
    }
    __syncthreads();   // XB (x2) fully consumed

    // ---- load mask + bias table into XB alias ----
    {
        const float* mw = mask + (size_t)(b & 1023) * (NWIN * NWIN);
#pragma unroll
        for (int i = tid; i < NWIN * NWIN; i += 384) MS[i] = mw[i];
        for (int i = tid; i < 225 * 6; i += 384) TS[i] = table[i];
    }
    __syncthreads();

    // ======================= Attention =======================
    // 24 subtasks = 6 heads x 4 row-quarters (16 rows); 12 warps x 2 iterations.
    // iter0 covers heads 0-2 (writes O cols 0..95), iter1 heads 3-5 -> Q slices
    // read in iter1 are disjoint from O written in iter0: no sync needed.
#pragma unroll
    for (int it = 0; it < 2; it++) {
        int st = wid + it * 12;
        int h = st >> 2, q4 = st & 3;
        int nrow0 = q4 * 16;

        unsigned qa[2][4];
        {
            unsigned base = qb_u + (((nrow0 + (lane & 15)) * LDW) + h * 32 + ((lane >> 4) * 8)) * 2;
            LDM_X4(qa[0], base);
            LDM_X4(qa[1], base + 16 * 2);
        }

        // S = Q K^T  (16 x 64)
        float s[8][4];
#pragma unroll
        for (int nt = 0; nt < 8; nt++)
#pragma unroll
            for (int r = 0; r < 4; r++) s[nt][r] = 0.f;
        {
            unsigned kbase = kb_u + (((lane & 7) * LDW) + h * 32 + (((lane >> 3) & 1) * 8)) * 2;
#pragma unroll
            for (int nt = 0; nt < 8; nt++) {
                unsigned B0[2], B1[2];
                LDM_X2(B0, kbase + nt * 8 * LDW * 2);
                LDM_X2(B1, kbase + nt * 8 * LDW * 2 + 16 * 2);
                MMA_F16(s[nt], qa[0], B0);
                MMA_F16(s[nt], qa[1], B1);
            }
        }

        // + relative-position bias + mask
#pragma unroll
        for (int hi = 0; hi < 2; hi++) {
            int n = nrow0 + hi * 8 + rq;
            int pr = n >> 3, pc = n & 7;
#pragma unroll
            for (int nt = 0; nt < 8; nt++)
#pragma unroll
                for (int e = 0; e < 2; e++) {
                    int m = nt * 8 + cq + e;
                    int idx = (pr - (m >> 3) + 7) * 15 + (pc - (m & 7) + 7);
                    s[nt][hi * 2 + e] += TS[idx * 6 + h] + MS[n * 64 + m];
                }
        }

        // softmax over 64 cols (row spread across 4 lanes -> quad shuffles)
#pragma unroll
        for (int hi = 0; hi < 2; hi++) {
            float mx = -1e30f;
#pragma unroll
            for (int nt = 0; nt < 8; nt++)
                mx = fmaxf(mx, fmaxf(s[nt][hi * 2], s[nt][hi * 2 + 1]));
            mx = fmaxf(mx, __shfl_xor_sync(0xffffffffu, mx, 1));
            mx = fmaxf(mx, __shfl_xor_sync(0xffffffffu, mx, 2));
            float sum = 0.f;
#pragma unroll
            for (int nt = 0; nt < 8; nt++) {
                float p0 = __expf(s[nt][hi * 2]     - mx);
                float p1 = __expf(s[nt][hi * 2 + 1] - mx);
                s[nt][hi * 2] = p0; s[nt][hi * 2 + 1] = p1;
                sum += p0 + p1;
            }
            sum += __shfl_xor_sync(0xffffffffu, sum, 1);
            sum += __shfl_xor_sync(0xffffffffu, sum, 2);
            float inv = 1.f / sum;
#pragma unroll
            for (int nt = 0; nt < 8; nt++) {
                s[nt][hi * 2] *= inv; s[nt][hi * 2 + 1] *= inv;
            }
        }

        // pack P (accumulator layout == next mma A layout)
        unsigned pk[8][2];
#pragma unroll
        for (int nt = 0; nt < 8; nt++) {
            pk[nt][0] = pack_half2(s[nt][0], s[nt][1]);
            pk[nt][1] = pack_half2(s[nt][2], s[nt][3]);
        }

        // O = P V  (16 x 32)
        float o[4][4];
#pragma unroll
        for (int dt = 0; dt < 4; dt++)
#pragma unroll
            for (int r = 0; r < 4; r++) o[dt][r] = 0.f;
#pragma unroll
        for (int j = 0; j < 4; j++) {
            unsigned vb[4][2];
            unsigned vbase = vb_u + (((j * 16 + (lane & 15)) * LDW) + h * 32) * 2;
#pragma unroll
            for (int dt = 0; dt < 4; dt++) LDM_X2T(vb[dt], vbase + dt * 8 * 2);
            unsigned pa[4] = { pk[2 * j][0], pk[2 * j][1],
                               pk[2 * j + 1][0], pk[2 * j + 1][1] };
#pragma unroll
            for (int dt = 0; dt < 4; dt++) MMA_F16(o[dt], pa, vb[dt]);
        }

        // write O over this subtask's Q slice
#pragma unroll
        for (int dt = 0; dt < 4; dt++) {
            int row = nrow0 + rq;
            int col = h * 32 + dt * 8 + cq;
            QB[row * LDW + col]           = __float2half_rn(o[dt][0]);
            QB[row * LDW + col + 1]       = __float2half_rn(o[dt][1]);
            QB[(row + 8) * LDW + col]     = __float2half_rn(o[dt][2]);
            QB[(row + 8) * LDW + col + 1] = __float2half_rn(o[dt][3]);
        }
    }
    __syncthreads();   // all O visible before projection

    // ======================= Output projection (1 round) ==================
    {
        float acc[4][2][4];
        gemm64x16(qb_u, g_bp + wid * (KSTEPS * 32), lane, acc);
        int colb = wid * 16;
        float* ob = out + (size_t)b * NWIN * DIM;
#pragma unroll
        for (int mt = 0; mt < 4; mt++)
#pragma unroll
            for (int n8 = 0; n8 < 2; n8++) {
                int row = mt * 16 + rq;
                int col = colb + n8 * 8 + cq;
                float bb0 = proj_b[col], bb1 = proj_b[col + 1];
                float* o0 = ob + (size_t)row * DIM + col;
                float* o1 = ob + (size_t)(row + 8) * DIM + col;
                o0[0] = acc[mt][n8][0] + bb0;
                o0[1] = acc[mt][n8][1] + bb1;
                o1[0] = acc[mt][n8][2] + bb0;
                o1[1] = acc[mt][n8][3] + bb1;
            }
    }
}

extern "C" void kernel_launch(void* const* d_in, const int* in_sizes, int n_in,
                              void* d_out, int out_size) {
    const float* x1     = (const float*)d_in[0];
    const float* x2     = (const float*)d_in[1];
    const float* mask   = (const float*)d_in[2];
    const float* q_w    = (const float*)d_in[3];
    const float* q_b    = (const float*)d_in[4];
    const float* kv_w   = (const float*)d_in[5];
    const float* kv_b   = (const float*)d_in[6];
    const float* proj_w = (const float*)d_in[7];
    const float* proj_b = (const float*)d_in[8];
    const float* table  = (const float*)d_in[9];

    prep_kernel<<<72, 256>>>(q_w, kv_w, proj_w);

    cudaFuncSetAttribute(wca_kernel, cudaFuncAttributeMaxDynamicSharedMemorySize, SMEM_TOTAL);
    wca_kernel<<<8192, 384, SMEM_TOTAL>>>(x1, x2, mask, q_b, kv_b, proj_b, table,
                                          (float*)d_out);
}

// round 11
// speedup vs baseline: 2.3854x; 1.1207x over previous
#include <cuda_runtime.h>
#include <cuda_fp16.h>

// ============================================================================
// Fused window cross-attention (fp16 mma.sync, fp32 accum), v3:
//  - 1 window per CTA (grid 8192), 384 threads, 102.4KB smem -> 2 CTAs/SM
//  - GEMM warp tiling 32Mx32N (2 mi x 6 ni): 2.0 L1-wavefronts per MMA
//  - weights pre-packed in mma B-fragment order, streamed via LDG.128 from L2
//  - vectorized half2/float2 epilogues
// ============================================================================

#define NUM_HEADS 6
#define HEAD_DIM  32
#define DIM       192
#define NWIN      64
#define SCALE_F   0.17677669529663687f   // 32^-0.5
#define KSTEPS    12                     // 192 / 16

#define LDW   200     // padded row length (fp16); 400B stride
#define LDWU  100

// SMEM layout (bytes): 4 buffers of 64*200*2 = 25600
#define XB_OFF   0          // x staging; later mask(fp32,16384B)+table(fp32,5400B @+16384)
#define QB_OFF   25600      // q, later O
#define KB_OFF   51200
#define VB_OFF   76800
#define SMEM_TOTAL 102400

// Weights in mma-B-fragment order: frag index ((t*12 + s)*32 + lane), uint4 each.
//   n  = t*16 + lane/4,  k0 = s*16 + (lane%4)*2
//   .x = half2(W[n][k0], W[n][k0+1])  .y = half2(W[n][k0+8], W[n][k0+9])
//   .z/.w = same with n+8
__device__ __align__(16) uint4 g_bq [12 * KSTEPS * 32];
__device__ __align__(16) uint4 g_bkv[24 * KSTEPS * 32];
__device__ __align__(16) uint4 g_bp [12 * KSTEPS * 32];

static __device__ __forceinline__ unsigned pack_half2(float a, float b) {
    __half2 h = __floats2half2_rn(a, b);
    return *(unsigned*)&h;
}

static __device__ __forceinline__ uint4 make_frag(const float* __restrict__ W,
                                                  int t, int s, int l) {
    int n  = t * 16 + (l >> 2);
    int k0 = s * 16 + (l & 3) * 2;
    const float* r0 = W + (size_t)n * DIM;
    const float* r1 = W + (size_t)(n + 8) * DIM;
    uint4 u;
    u.x = pack_half2(r0[k0],     r0[k0 + 1]);
    u.y = pack_half2(r0[k0 + 8], r0[k0 + 9]);
    u.z = pack_half2(r1[k0],     r1[k0 + 1]);
    u.w = pack_half2(r1[k0 + 8], r1[k0 + 9]);
    return u;
}

__global__ void prep_kernel(const float* __restrict__ qw,
                            const float* __restrict__ kvw,
                            const float* __restrict__ pw) {
    int i = blockIdx.x * blockDim.x + threadIdx.x;   // 18432 total
    if (i < 4608) {
        int t = i / 384, r = i % 384, s = r / 32, l = r % 32;
        g_bq[i] = make_frag(qw, t, s, l);
    } else if (i < 13824) {
        int j = i - 4608;
        int t = j / 384, r = j % 384, s = r / 32, l = r % 32;
        g_bkv[j] = make_frag(kvw, t, s, l);
    } else if (i < 18432) {
        int j = i - 13824;
        int t = j / 384, r = j % 384, s = r / 32, l = r % 32;
        g_bp[j] = make_frag(pw, t, s, l);
    }
}

static __device__ __forceinline__ unsigned sm_u32(const void* p) {
    return (unsigned)__cvta_generic_to_shared(p);
}

#define LDM_X4(R, ADDR) \
    asm volatile("ldmatrix.sync.aligned.m8n8.x4.shared.b16 {%0,%1,%2,%3}, [%4];" \
                 : "=r"((R)[0]), "=r"((R)[1]), "=r"((R)[2]), "=r"((R)[3]) : "r"(ADDR))
#define LDM_X2(R, ADDR) \
    asm volatile("ldmatrix.sync.aligned.m8n8.x2.shared.b16 {%0,%1}, [%2];" \
                 : "=r"((R)[0]), "=r"((R)[1]) : "r"(ADDR))
#define LDM_X2T(R, ADDR) \
    asm volatile("ldmatrix.sync.aligned.m8n8.x2.trans.shared.b16 {%0,%1}, [%2];" \
                 : "=r"((R)[0]), "=r"((R)[1]) : "r"(ADDR))
#define MMA_F16(D, A, B) \
    asm volatile("mma.sync.aligned.m16n8k16.row.col.f32.f16.f16.f32 " \
                 "{%0,%1,%2,%3},{%4,%5,%6,%7},{%8,%9},{%0,%1,%2,%3};" \
                 : "+f"((D)[0]), "+f"((D)[1]), "+f"((D)[2]), "+f"((D)[3]) \
                 : "r"((A)[0]), "r"((A)[1]), "r"((A)[2]), "r"((A)[3]), \
                   "r"((B)[0]), "r"((B)[1]))

// 32(M) x 32(N) x 192(K) warp GEMM: A fp16 in smem (row stride LDW, rows mrow0..+31),
// B fragments streamed from gmem: bt0 covers cols [n0, n0+16), bt1 [n0+16, n0+32).
// acc[mt][n8][4]: mt = 16-row tile (2), n8 = 8-col tile (4).
static __device__ __forceinline__ void gemm32x32(unsigned a_u, int mrow0,
                                                 const uint4* __restrict__ bt0,
                                                 const uint4* __restrict__ bt1,
                                                 int lane, float acc[2][4][4]) {
#pragma unroll
    for (int mt = 0; mt < 2; mt++)
#pragma unroll
        for (int n8 = 0; n8 < 4; n8++)
#pragma unroll
            for (int r = 0; r < 4; r++) acc[mt][n8][r] = 0.f;

    const unsigned aAddr = a_u + (((mrow0 + (lane & 15)) * LDW + (lane >> 4) * 8) * 2);
    uint4 b0c = bt0[lane], b1c = bt1[lane];
#pragma unroll
    for (int s = 0; s < KSTEPS; s++) {
        uint4 b0n = (s + 1 < KSTEPS) ? bt0[(s + 1) * 32 + lane] : b0c;
        uint4 b1n = (s + 1 < KSTEPS) ? bt1[(s + 1) * 32 + lane] : b1c;
        unsigned B0[2] = { b0c.x, b0c.y };
        unsigned B1[2] = { b0c.z, b0c.w };
        unsigned B2[2] = { b1c.x, b1c.y };
        unsigned B3[2] = { b1c.z, b1c.w };
#pragma unroll
        for (int mt = 0; mt < 2; mt++) {
            unsigned A[4];
            LDM_X4(A, aAddr + (s * 16) * 2 + mt * (16 * LDW * 2));
            MMA_F16(acc[mt][0], A, B0);
            MMA_F16(acc[mt][1], A, B1);
            MMA_F16(acc[mt][2], A, B2);
            MMA_F16(acc[mt][3], A, B3);
        }
        b0c = b0n; b1c = b1n;
    }
}

__global__ void __launch_bounds__(384, 2)
wca_kernel(const float* __restrict__ x1, const float* __restrict__ x2,
           const float* __restrict__ mask,
           const float* __restrict__ q_b, const float* __restrict__ kv_b,
           const float* __restrict__ proj_b, const float* __restrict__ table,
           float* __restrict__ out) {
    extern __shared__ __align__(16) unsigned char smem[];
    __half* XB = (__half*)(smem + XB_OFF);
    __half* QB = (__half*)(smem + QB_OFF);
    __half* KB = (__half*)(smem + KB_OFF);
    __half* VB = (__half*)(smem + VB_OFF);
    float*  MS = (float*)(smem + XB_OFF);            // 64*64*4 = 16384, aliases XB
    float*  TS = (float*)(smem + XB_OFF + 16384);    // 225*6*4 = 5400,  aliases XB

    const int tid  = threadIdx.x;
    const int lane = tid & 31;
    const int wid  = tid >> 5;
    const int b    = blockIdx.x;                     // one window

    const unsigned xb_u = sm_u32(XB), qb_u = sm_u32(QB);
    const unsigned kb_u = sm_u32(KB), vb_u = sm_u32(VB);
    const int rq = lane >> 2;            // 0..7
    const int cq = (lane & 3) * 2;       // 0,2,4,6

    // GEMM warp tiling: 2 mi (32 rows) x 6 ni (32 cols)
    const int mi = wid & 1;
    const int ni = wid >> 1;             // 0..5
    const int mrow0 = mi * 32;

    // ---- load x1 (64 x 192 fp32 -> fp16 smem) ----
    {
        const float4* src = (const float4*)(x1 + (size_t)b * NWIN * DIM);
        unsigned* xbu = (unsigned*)XB;
#pragma unroll
        for (int i = tid; i < 64 * 48; i += 384) {
            int r = i / 48, c = i % 48;
            float4 v = src[i];
            xbu[r * LDWU + c * 2]     = pack_half2(v.x, v.y);
            xbu[r * LDWU + c * 2 + 1] = pack_half2(v.z, v.w);
        }
    }
    __syncthreads();

    // ======================= Q projection (1 round) =======================
    {
        float acc[2][4][4];
        gemm32x32(xb_u, mrow0, g_bq + (2 * ni) * (KSTEPS * 32),
                  g_bq + (2 * ni + 1) * (KSTEPS * 32), lane, acc);
        int colb = ni * 32;
#pragma unroll
        for (int mt = 0; mt < 2; mt++)
#pragma unroll
            for (int n8 = 0; n8 < 4; n8++) {
                int row = mrow0 + mt * 16 + rq;
                int col = colb + n8 * 8 + cq;
                float2 bb = *(const float2*)(q_b + col);
                *(unsigned*)(QB + row * LDW + col) =
                    pack_half2((acc[mt][n8][0] + bb.x) * SCALE_F,
                               (acc[mt][n8][1] + bb.y) * SCALE_F);
                *(unsigned*)(QB + (row + 8) * LDW + col) =
                    pack_half2((acc[mt][n8][2] + bb.x) * SCALE_F,
                               (acc[mt][n8][3] + bb.y) * SCALE_F);
            }
    }
    __syncthreads();   // XB (x1) fully consumed

    // ---- load x2 into XB ----
    {
        const float4* src = (const float4*)(x2 + (size_t)b * NWIN * DIM);
        unsigned* xbu = (unsigned*)XB;
#pragma unroll
        for (int i = tid; i < 64 * 48; i += 384) {
            int r = i / 48, c = i % 48;
            float4 v = src[i];
            xbu[r * LDWU + c * 2]     = pack_half2(v.x, v.y);
            xbu[r * LDWU + c * 2 + 1] = pack_half2(v.z, v.w);
        }
    }
    __syncthreads();

    // ======================= K / V projection (2 iterations) ===============
#pragma unroll
    for (int it = 0; it < 2; it++) {
        int t0 = it * 12 + 2 * ni;        // fragment tile pair
        float acc[2][4][4];
        gemm32x32(xb_u, mrow0, g_bkv + t0 * (KSTEPS * 32),
                  g_bkv + (t0 + 1) * (KSTEPS * 32), lane, acc);
        __half* OB = it ? VB : KB;
        int cgb  = it * 192 + ni * 32;    // global output channel base
        int colb = ni * 32;               // local column base in K/V buffer
#pragma unroll
        for (int mt = 0; mt < 2; mt++)
#pragma unroll
            for (int n8 = 0; n8 < 4; n8++) {
                int row = mrow0 + mt * 16 + rq;
                int c8  = n8 * 8 + cq;
                float2 bb = *(const float2*)(kv_b + cgb + c8);
                int col = colb + c8;
                *(unsigned*)(OB + row * LDW + col) =
                    pack_half2(acc[mt][n8][0] + bb.x, acc[mt][n8][1] + bb.y);
                *(unsigned*)(OB + (row + 8) * LDW + col) =
                    pack_half2(acc[mt][n8][2] + bb.x, acc[mt][n8][3] + bb.y);
            }
    }
    __syncthreads();   // XB (x2) fully consumed

    // ---- load mask (float4) + bias table into XB alias ----
    {
        const float4* mw = (const float4*)(mask + (size_t)(b & 1023) * (NWIN * NWIN));
        float4* ms4 = (float4*)MS;
#pragma unroll
        for (int i = tid; i < NWIN * NWIN / 4; i += 384) ms4[i] = mw[i];
        for (int i = tid; i < 225 * 6; i += 384) TS[i] = table[i];
    }
    __syncthreads();

    // ======================= Attention =======================
    // 24 subtasks = 6 heads x 4 row-quarters (16 rows); 12 warps x 2 iterations.
    // iter0 = heads 0-2 (O cols 0..95), iter1 = heads 3-5: Q slices read in
    // iter1 are disjoint from O written in iter0 -> no sync needed.
#pragma unroll
    for (int it = 0; it < 2; it++) {
        int st = wid + it * 12;
        int h = st >> 2, q4 = st & 3;
        int nrow0 = q4 * 16;

        unsigned qa[2][4];
        {
            unsigned base = qb_u + (((nrow0 + (lane & 15)) * LDW) + h * 32 + ((lane >> 4) * 8)) * 2;
            LDM_X4(qa[0], base);
            LDM_X4(qa[1], base + 16 * 2);
        }

        // S = Q K^T  (16 x 64)
        float s[8][4];
#pragma unroll
        for (int nt = 0; nt < 8; nt++)
#pragma unroll
            for (int r = 0; r < 4; r++) s[nt][r] = 0.f;
        {
            unsigned kbase = kb_u + (((lane & 7) * LDW) + h * 32 + (((lane >> 3) & 1) * 8)) * 2;
#pragma unroll
            for (int nt = 0; nt < 8; nt++) {
                unsigned B0[2], B1[2];
                LDM_X2(B0, kbase + nt * 8 * LDW * 2);
                LDM_X2(B1, kbase + nt * 8 * LDW * 2 + 16 * 2);
                MMA_F16(s[nt], qa[0], B0);
                MMA_F16(s[nt], qa[1], B1);
            }
        }

        // + relative-position bias + mask
#pragma unroll
        for (int hi = 0; hi < 2; hi++) {
            int n = nrow0 + hi * 8 + rq;
            int pr = n >> 3, pc = n & 7;
#pragma unroll
            for (int nt = 0; nt < 8; nt++)
#pragma unroll
                for (int e = 0; e < 2; e++) {
                    int m = nt * 8 + cq + e;
                    int idx = (pr - (m >> 3) + 7) * 15 + (pc - (m & 7) + 7);
                    s[nt][hi * 2 + e] += TS[idx * 6 + h] + MS[n * 64 + m];
                }
        }

        // softmax over 64 cols (row spread across 4 lanes -> quad shuffles)
#pragma unroll
        for (int hi = 0; hi < 2; hi++) {
            float mx = -1e30f;
#pragma unroll
            for (int nt = 0; nt < 8; nt++)
                mx = fmaxf(mx, fmaxf(s[nt][hi * 2], s[nt][hi * 2 + 1]));
            mx = fmaxf(mx, __shfl_xor_sync(0xffffffffu, mx, 1));
            mx = fmaxf(mx, __shfl_xor_sync(0xffffffffu, mx, 2));
            float sum = 0.f;
#pragma unroll
            for (int nt = 0; nt < 8; nt++) {
                float p0 = __expf(s[nt][hi * 2]     - mx);
                float p1 = __expf(s[nt][hi * 2 + 1] - mx);
                s[nt][hi * 2] = p0; s[nt][hi * 2 + 1] = p1;
                sum += p0 + p1;
            }
            sum += __shfl_xor_sync(0xffffffffu, sum, 1);
            sum += __shfl_xor_sync(0xffffffffu, sum, 2);
            float inv = 1.f / sum;
#pragma unroll
            for (int nt = 0; nt < 8; nt++) {
                s[nt][hi * 2] *= inv; s[nt][hi * 2 + 1] *= inv;
            }
        }

        // pack P (accumulator layout == next mma A layout)
        unsigned pk[8][2];
#pragma unroll
        for (int nt = 0; nt < 8; nt++) {
            pk[nt][0] = pack_half2(s[nt][0], s[nt][1]);
            pk[nt][1] = pack_half2(s[nt][2], s[nt][3]);
        }

        // O = P V  (16 x 32)
        float o[4][4];
#pragma unroll
        for (int dt = 0; dt < 4; dt++)
#pragma unroll
            for (int r = 0; r < 4; r++) o[dt][r] = 0.f;
#pragma unroll
        for (int j = 0; j < 4; j++) {
            unsigned vb[4][2];
            unsigned vbase = vb_u + (((j * 16 + (lane & 15)) * LDW) + h * 32) * 2;
#pragma unroll
            for (int dt = 0; dt < 4; dt++) LDM_X2T(vb[dt], vbase + dt * 8 * 2);
            unsigned pa[4] = { pk[2 * j][0], pk[2 * j][1],
                               pk[2 * j + 1][0], pk[2 * j + 1][1] };
#pragma unroll
            for (int dt = 0; dt < 4; dt++) MMA_F16(o[dt], pa, vb[dt]);
        }

        // write O over this subtask's Q slice (half2 stores)
#pragma unroll
        for (int dt = 0; dt < 4; dt++) {
            int row = nrow0 + rq;
            int col = h * 32 + dt * 8 + cq;
            *(unsigned*)(QB + row * LDW + col)       = pack_half2(o[dt][0], o[dt][1]);
            *(unsigned*)(QB + (row + 8) * LDW + col) = pack_half2(o[dt][2], o[dt][3]);
        }
    }
    __syncthreads();   // all O visible before projection

    // ======================= Output projection (1 round) ==================
    {
        float acc[2][4][4];
        gemm32x32(qb_u, mrow0, g_bp + (2 * ni) * (KSTEPS * 32),
                  g_bp + (2 * ni + 1) * (KSTEPS * 32), lane, acc);
        int colb = ni * 32;
        float* ob = out + (size_t)b * NWIN * DIM;
#pragma unroll
        for (int mt = 0; mt < 2; mt++)
#pragma unroll
            for (int n8 = 0; n8 < 4; n8++) {
                int row = mrow0 + mt * 16 + rq;
                int col = colb + n8 * 8 + cq;
                float2 bb = *(const float2*)(proj_b + col);
                float2 r0 = make_float2(acc[mt][n8][0] + bb.x, acc[mt][n8][1] + bb.y);
                float2 r1 = make_float2(acc[mt][n8][2] + bb.x, acc[mt][n8][3] + bb.y);
                *(float2*)(ob + (size_t)row * DIM + col)       = r0;
                *(float2*)(ob + (size_t)(row + 8) * DIM + col) = r1;
            }
    }
}

extern "C" void kernel_launch(void* const* d_in, const int* in_sizes, int n_in,
                              void* d_out, int out_size) {
    const float* x1     = (const float*)d_in[0];
    const float* x2     = (const float*)d_in[1];
    const float* mask   = (const float*)d_in[2];
    const float* q_w    = (const float*)d_in[3];
    const float* q_b    = (const float*)d_in[4];
    const float* kv_w   = (const float*)d_in[5];
    const float* kv_b   = (const float*)d_in[6];
    const float* proj_w = (const float*)d_in[7];
    const float* proj_b = (const float*)d_in[8];
    const float* table  = (const float*)d_in[9];

    prep_kernel<<<72, 256>>>(q_w, kv_w, proj_w);

    cudaFuncSetAttribute(wca_kernel, cudaFuncAttributeMaxDynamicSharedMemorySize, SMEM_TOTAL);
    wca_kernel<<<8192, 384, SMEM_TOTAL>>>(x1, x2, mask, q_b, kv_b, proj_b, table,
                                          (float*)d_out);
}

// round 14
// speedup vs baseline: 2.4766x; 1.0382x over previous
#include <cuda_runtime.h>
#include <cuda_fp16.h>

// ============================================================================
// Fused window cross-attention (fp16 mma.sync, fp32 accum), v4:
//  - v3 + mask staged as half2 with padded row stride (33 words) -> the mask
//    add goes from 8-way-conflicted scalar LDS (6144 wf/CTA) to conflict-free
//    u32 LDS (384 wf/CTA)
//  - simplified bias-index arithmetic, STS.64 x-staging
// ============================================================================

#define NUM_HEADS 6
#define HEAD_DIM  32
#define DIM       192
#define NWIN      64
#define SCALE_F   0.17677669529663687f   // 32^-0.5
#define KSTEPS    12                     // 192 / 16

#define LDW   200     // padded row length (fp16); 400B stride
#define LDWU  100
#define LDM2  33      // mask row stride in half2 words (33*4B -> conflict-free)

// SMEM layout (bytes): 4 buffers of 64*200*2 = 25600
#define XB_OFF   0          // x staging; later mask-half2 (64*33*4=8448B) + table fp32 @+16384
#define QB_OFF   25600      // q, later O
#define KB_OFF   51200
#define VB_OFF   76800
#define SMEM_TOTAL 102400

// Weights in mma-B-fragment order: frag index ((t*12 + s)*32 + lane), uint4 each.
__device__ __align__(16) uint4 g_bq [12 * KSTEPS * 32];
__device__ __align__(16) uint4 g_bkv[24 * KSTEPS * 32];
__device__ __align__(16) uint4 g_bp [12 * KSTEPS * 32];

static __device__ __forceinline__ unsigned pack_half2(float a, float b) {
    __half2 h = __floats2half2_rn(a, b);
    return *(unsigned*)&h;
}

static __device__ __forceinline__ uint4 make_frag(const float* __restrict__ W,
                                                  int t, int s, int l) {
    int n  = t * 16 + (l >> 2);
    int k0 = s * 16 + (l & 3) * 2;
    const float* r0 = W + (size_t)n * DIM;
    const float* r1 = W + (size_t)(n + 8) * DIM;
    uint4 u;
    u.x = pack_half2(r0[k0],     r0[k0 + 1]);
    u.y = pack_half2(r0[k0 + 8], r0[k0 + 9]);
    u.z = pack_half2(r1[k0],     r1[k0 + 1]);
    u.w = pack_half2(r1[k0 + 8], r1[k0 + 9]);
    return u;
}

__global__ void prep_kernel(const float* __restrict__ qw,
                            const float* __restrict__ kvw,
                            const float* __restrict__ pw) {
    int i = blockIdx.x * blockDim.x + threadIdx.x;   // 18432 total
    if (i < 4608) {
        int t = i / 384, r = i % 384, s = r / 32, l = r % 32;
        g_bq[i] = make_frag(qw, t, s, l);
    } else if (i < 13824) {
        int j = i - 4608;
        int t = j / 384, r = j % 384, s = r / 32, l = r % 32;
        g_bkv[j] = make_frag(kvw, t, s, l);
    } else if (i < 18432) {
        int j = i - 13824;
        int t = j / 384, r = j % 384, s = r / 32, l = r % 32;
        g_bp[j] = make_frag(pw, t, s, l);
    }
}

static __device__ __forceinline__ unsigned sm_u32(const void* p) {
    return (unsigned)__cvta_generic_to_shared(p);
}

#define LDM_X4(R, ADDR) \
    asm volatile("ldmatrix.sync.aligned.m8n8.x4.shared.b16 {%0,%1,%2,%3}, [%4];" \
                 : "=r"((R)[0]), "=r"((R)[1]), "=r"((R)[2]), "=r"((R)[3]) : "r"(ADDR))
#define LDM_X2(R, ADDR) \
    asm volatile("ldmatrix.sync.aligned.m8n8.x2.shared.b16 {%0,%1}, [%2];" \
                 : "=r"((R)[0]), "=r"((R)[1]) : "r"(ADDR))
#define LDM_X2T(R, ADDR) \
    asm volatile("ldmatrix.sync.aligned.m8n8.x2.trans.shared.b16 {%0,%1}, [%2];" \
                 : "=r"((R)[0]), "=r"((R)[1]) : "r"(ADDR))
#define MMA_F16(D, A, B) \
    asm volatile("mma.sync.aligned.m16n8k16.row.col.f32.f16.f16.f32 " \
                 "{%0,%1,%2,%3},{%4,%5,%6,%7},{%8,%9},{%0,%1,%2,%3};" \
                 : "+f"((D)[0]), "+f"((D)[1]), "+f"((D)[2]), "+f"((D)[3]) \
                 : "r"((A)[0]), "r"((A)[1]), "r"((A)[2]), "r"((A)[3]), \
                   "r"((B)[0]), "r"((B)[1]))

// 32(M) x 32(N) x 192(K) warp GEMM: A fp16 in smem, B fragments from gmem.
static __device__ __forceinline__ void gemm32x32(unsigned a_u, int mrow0,
                                                 const uint4* __restrict__ bt0,
                                                 const uint4* __restrict__ bt1,
                                                 int lane, float acc[2][4][4]) {
#pragma unroll
    for (int mt = 0; mt < 2; mt++)
#pragma unroll
        for (int n8 = 0; n8 < 4; n8++)
#pragma unroll
            for (int r = 0; r < 4; r++) acc[mt][n8][r] = 0.f;

    const unsigned aAddr = a_u + (((mrow0 + (lane & 15)) * LDW + (lane >> 4) * 8) * 2);
    uint4 b0c = bt0[lane], b1c = bt1[lane];
#pragma unroll
    for (int s = 0; s < KSTEPS; s++) {
        uint4 b0n = (s + 1 < KSTEPS) ? bt0[(s + 1) * 32 + lane] : b0c;
        uint4 b1n = (s + 1 < KSTEPS) ? bt1[(s + 1) * 32 + lane] : b1c;
        unsigned B0[2] = { b0c.x, b0c.y };
        unsigned B1[2] = { b0c.z, b0c.w };
        unsigned B2[2] = { b1c.x, b1c.y };
        unsigned B3[2] = { b1c.z, b1c.w };
#pragma unroll
        for (int mt = 0; mt < 2; mt++) {
            unsigned A[4];
            LDM_X4(A, aAddr + (s * 16) * 2 + mt * (16 * LDW * 2));
            MMA_F16(acc[mt][0], A, B0);
            MMA_F16(acc[mt][1], A, B1);
            MMA_F16(acc[mt][2], A, B2);
            MMA_F16(acc[mt][3], A, B3);
        }
        b0c = b0n; b1c = b1n;
    }
}

__global__ void __launch_bounds__(384, 2)
wca_kernel(const float* __restrict__ x1, const float* __restrict__ x2,
           const float* __restrict__ mask,
           const float* __restrict__ q_b, const float* __restrict__ kv_b,
           const float* __restrict__ proj_b, const float* __restrict__ table,
           float* __restrict__ out) {
    extern __shared__ __align__(16) unsigned char smem[];
    __half* XB = (__half*)(smem + XB_OFF);
    __half* QB = (__half*)(smem + QB_OFF);
    __half* KB = (__half*)(smem + KB_OFF);
    __half* VB = (__half*)(smem + VB_OFF);
    unsigned* MH = (unsigned*)(smem + XB_OFF);       // mask as half2, 64*33*4 = 8448B
    float*  TS = (float*)(smem + XB_OFF + 16384);    // 225*6*4 = 5400B

    const int tid  = threadIdx.x;
    const int lane = tid & 31;
    const int wid  = tid >> 5;
    const int b    = blockIdx.x;                     // one window

    const unsigned xb_u = sm_u32(XB), qb_u = sm_u32(QB);
    const unsigned kb_u = sm_u32(KB), vb_u = sm_u32(VB);
    const int rq = lane >> 2;            // 0..7
    const int cq = (lane & 3) * 2;       // 0,2,4,6

    // GEMM warp tiling: 2 mi (32 rows) x 6 ni (32 cols)
    const int mi = wid & 1;
    const int ni = wid >> 1;             // 0..5
    const int mrow0 = mi * 32;

    // ---- load x1 (64 x 192 fp32 -> fp16 smem) ----
    {
        const float4* src = (const float4*)(x1 + (size_t)b * NWIN * DIM);
        unsigned* xbu = (unsigned*)XB;
#pragma unroll
        for (int i = tid; i < 64 * 48; i += 384) {
            int r = i / 48, c = i % 48;
            float4 v = src[i];
            *(uint2*)(xbu + r * LDWU + c * 2) =
                make_uint2(pack_half2(v.x, v.y), pack_half2(v.z, v.w));
        }
    }
    __syncthreads();

    // ======================= Q projection (1 round) =======================
    {
        float acc[2][4][4];
        gemm32x32(xb_u, mrow0, g_bq + (2 * ni) * (KSTEPS * 32),
                  g_bq + (2 * ni + 1) * (KSTEPS * 32), lane, acc);
        int colb = ni * 32;
#pragma unroll
        for (int mt = 0; mt < 2; mt++)
#pragma unroll
            for (int n8 = 0; n8 < 4; n8++) {
                int row = mrow0 + mt * 16 + rq;
                int col = colb + n8 * 8 + cq;
                float2 bb = *(const float2*)(q_b + col);
                *(unsigned*)(QB + row * LDW + col) =
                    pack_half2((acc[mt][n8][0] + bb.x) * SCALE_F,
                               (acc[mt][n8][1] + bb.y) * SCALE_F);
                *(unsigned*)(QB + (row + 8) * LDW + col) =
                    pack_half2((acc[mt][n8][2] + bb.x) * SCALE_F,
                               (acc[mt][n8][3] + bb.y) * SCALE_F);
            }
    }
    __syncthreads();   // XB (x1) fully consumed

    // ---- load x2 into XB ----
    {
        const float4* src = (const float4*)(x2 + (size_t)b * NWIN * DIM);
        unsigned* xbu = (unsigned*)XB;
#pragma unroll
        for (int i = tid; i < 64 * 48; i += 384) {
            int r = i / 48, c = i % 48;
            float4 v = src[i];
            *(uint2*)(xbu + r * LDWU + c * 2) =
                make_uint2(pack_half2(v.x, v.y), pack_half2(v.z, v.w));
        }
    }
    __syncthreads();

    // ======================= K / V projection (2 iterations) ===============
#pragma unroll
    for (int it = 0; it < 2; it++) {
        int t0 = it * 12 + 2 * ni;        // fragment tile pair
        float acc[2][4][4];
        gemm32x32(xb_u, mrow0, g_bkv + t0 * (KSTEPS * 32),
                  g_bkv + (t0 + 1) * (KSTEPS * 32), lane, acc);
        __half* OB = it ? VB : KB;
        int cgb  = it * 192 + ni * 32;    // global output channel base
        int colb = ni * 32;               // local column base in K/V buffer
#pragma unroll
        for (int mt = 0; mt < 2; mt++)
#pragma unroll
            for (int n8 = 0; n8 < 4; n8++) {
                int row = mrow0 + mt * 16 + rq;
                int c8  = n8 * 8 + cq;
                float2 bb = *(const float2*)(kv_b + cgb + c8);
                int col = colb + c8;
                *(unsigned*)(OB + row * LDW + col) =
                    pack_half2(acc[mt][n8][0] + bb.x, acc[mt][n8][1] + bb.y);
                *(unsigned*)(OB + (row + 8) * LDW + col) =
                    pack_half2(acc[mt][n8][2] + bb.x, acc[mt][n8][3] + bb.y);
            }
    }
    __syncthreads();   // XB (x2) fully consumed

    // ---- stage mask (fp32 -> half2, padded stride) + bias table ----
    {
        const float2* mw = (const float2*)(mask + (size_t)(b & 1023) * (NWIN * NWIN));
#pragma unroll
        for (int i = tid; i < 64 * 32; i += 384) {
            int n = i >> 5, j = i & 31;
            float2 v = mw[i];
            MH[n * LDM2 + j] = pack_half2(v.x, v.y);
        }
        for (int i = tid; i < 225 * 6; i += 384) TS[i] = table[i];
    }
    __syncthreads();

    // ======================= Attention =======================
    // 24 subtasks = 6 heads x 4 row-quarters (16 rows); 12 warps x 2 iterations.
    // iter0 = heads 0-2 (O cols 0..95), iter1 = heads 3-5: Q slices read in
    // iter1 are disjoint from O written in iter0 -> no sync needed.
#pragma unroll
    for (int it = 0; it < 2; it++) {
        int st = wid + it * 12;
        int h = st >> 2, q4 = st & 3;
        int nrow0 = q4 * 16;

        unsigned qa[2][4];
        {
            unsigned base = qb_u + (((nrow0 + (lane & 15)) * LDW) + h * 32 + ((lane >> 4) * 8)) * 2;
            LDM_X4(qa[0], base);
            LDM_X4(qa[1], base + 16 * 2);
        }

        // S = Q K^T  (16 x 64)
        float s[8][4];
#pragma unroll
        for (int nt = 0; nt < 8; nt++)
#pragma unroll
            for (int r = 0; r < 4; r++) s[nt][r] = 0.f;
        {
            unsigned kbase = kb_u + (((lane & 7) * LDW) + h * 32 + (((lane >> 3) & 1) * 8)) * 2;
#pragma unroll
            for (int nt = 0; nt < 8; nt++) {
                unsigned B0[2], B1[2];
                LDM_X2(B0, kbase + nt * 8 * LDW * 2);
                LDM_X2(B1, kbase + nt * 8 * LDW * 2 + 16 * 2);
                MMA_F16(s[nt], qa[0], B0);
                MMA_F16(s[nt], qa[1], B1);
            }
        }

        // + relative-position bias + mask (half2, conflict-free)
        // idx(e=0) = (pr-nt+7)*15 + (pc-cq+7);  idx(e=1) = idx(e=0) - 1
#pragma unroll
        for (int hi = 0; hi < 2; hi++) {
            int n  = nrow0 + hi * 8 + rq;
            int pr = n >> 3, pc = n & 7;
            int roff = (pr + 7) * 15 + (pc - cq + 7);
            int mb = n * LDM2 + (cq >> 1);
#pragma unroll
            for (int nt = 0; nt < 8; nt++) {
                int idx0 = roff - nt * 15;
                unsigned u = MH[mb + nt * 4];
                float2 mv = __half22float2(*(__half2*)&u);
                s[nt][hi * 2]     += TS[idx0 * 6 + h] + mv.x;
                s[nt][hi * 2 + 1] += TS[(idx0 - 1) * 6 + h] + mv.y;
            }
        }

        // softmax over 64 cols (row spread across 4 lanes -> quad shuffles)
#pragma unroll
        for (int hi = 0; hi < 2; hi++) {
            float mx = -1e30f;
#pragma unroll
            for (int nt = 0; nt < 8; nt++)
                mx = fmaxf(mx, fmaxf(s[nt][hi * 2], s[nt][hi * 2 + 1]));
            mx = fmaxf(mx, __shfl_xor_sync(0xffffffffu, mx, 1));
            mx = fmaxf(mx, __shfl_xor_sync(0xffffffffu, mx, 2));
            float sum = 0.f;
#pragma unroll
            for (int nt = 0; nt < 8; nt++) {
                float p0 = __expf(s[nt][hi * 2]     - mx);
                float p1 = __expf(s[nt][hi * 2 + 1] - mx);
                s[nt][hi * 2] = p0; s[nt][hi * 2 + 1] = p1;
                sum += p0 + p1;
            }
            sum += __shfl_xor_sync(0xffffffffu, sum, 1);
            sum += __shfl_xor_sync(0xffffffffu, sum, 2);
            float inv = 1.f / sum;
#pragma unroll
            for (int nt = 0; nt < 8; nt++) {
                s[nt][hi * 2] *= inv; s[nt][hi * 2 + 1] *= inv;
            }
        }

        // pack P (accumulator layout == next mma A layout)
        unsigned pk[8][2];
#pragma unroll
        for (int nt = 0; nt < 8; nt++) {
            pk[nt][0] = pack_half2(s[nt][0], s[nt][1]);
            pk[nt][1] = pack_half2(s[nt][2], s[nt][3]);
        }

        // O = P V  (16 x 32)
        float o[4][4];
#pragma unroll
        for (int dt = 0; dt < 4; dt++)
#pragma unroll
            for (int r = 0; r < 4; r++) o[dt][r] = 0.f;
#pragma unroll
        for (int j = 0; j < 4; j++) {
            unsigned vb[4][2];
            unsigned vbase = vb_u + (((j * 16 + (lane & 15)) * LDW) + h * 32) * 2;
#pragma unroll
            for (int dt = 0; dt < 4; dt++) LDM_X2T(vb[dt], vbase + dt * 8 * 2);
            unsigned pa[4] = { pk[2 * j][0], pk[2 * j][1],
                               pk[2 * j + 1][0], pk[2 * j + 1][1] };
#pragma unroll
            for (int dt = 0; dt < 4; dt++) MMA_F16(o[dt], pa, vb[dt]);
        }

        // write O over this subtask's Q slice (half2 stores)
#pragma unroll
        for (int dt = 0; dt < 4; dt++) {
            int row = nrow0 + rq;
            int col = h * 32 + dt * 8 + cq;
            *(unsigned*)(QB + row * LDW + col)       = pack_half2(o[dt][0], o[dt][1]);
            *(unsigned*)(QB + (row + 8) * LDW + col) = pack_half2(o[dt][2], o[dt][3]);
        }
    }
    __syncthreads();   // all O visible before projection

    // ======================= Output projection (1 round) ==================
    {
        float acc[2][4][4];
        gemm32x32(qb_u, mrow0, g_bp + (2 * ni) * (KSTEPS * 32),
                  g_bp + (2 * ni + 1) * (KSTEPS * 32), lane, acc);
        int colb = ni * 32;
        float* ob = out + (size_t)b * NWIN * DIM;
#pragma unroll
        for (int mt = 0; mt < 2; mt++)
#pragma unroll
            for (int n8 = 0; n8 < 4; n8++) {
                int row = mrow0 + mt * 16 + rq;
                int col = colb + n8 * 8 + cq;
                float2 bb = *(const float2*)(proj_b + col);
                float2 r0 = make_float2(acc[mt][n8][0] + bb.x, acc[mt][n8][1] + bb.y);
                float2 r1 = make_float2(acc[mt][n8][2] + bb.x, acc[mt][n8][3] + bb.y);
                *(float2*)(ob + (size_t)row * DIM + col)       = r0;
                *(float2*)(ob + (size_t)(row + 8) * DIM + col) = r1;
            }
    }
}

extern "C" void kernel_launch(void* const* d_in, const int* in_sizes, int n_in,
                              void* d_out, int out_size) {
    const float* x1     = (const float*)d_in[0];
    const float* x2     = (const float*)d_in[1];
    const float* mask   = (const float*)d_in[2];
    const float* q_w    = (const float*)d_in[3];
    const float* q_b    = (const float*)d_in[4];
    const float* kv_w   = (const float*)d_in[5];
    const float* kv_b   = (const float*)d_in[6];
    const float* proj_w = (const float*)d_in[7];
    const float* proj_b = (const float*)d_in[8];
    const float* table  = (const float*)d_in[9];

    prep_kernel<<<72, 256>>>(q_w, kv_w, proj_w);

    cudaFuncSetAttribute(wca_kernel, cudaFuncAttributeMaxDynamicSharedMemorySize, SMEM_TOTAL);
    wca_kernel<<<8192, 384, SMEM_TOTAL>>>(x1, x2, mask, q_b, kv_b, proj_b, table,
                                          (float*)d_out);
}

// round 17
// speedup vs baseline: 2.5617x; 1.0344x over previous
#include <cuda_runtime.h>
#include <cuda_fp16.h>

// ============================================================================
// Fused window cross-attention (fp16 mma.sync, fp32 accum), v6:
//  - v4 + truly conflict-free mask layout (LDM2=36: bank == lane) and
//    head-major bias table (no x6 bank multiplier)
//  - tcgen05 unavailable: harness compiles -arch=sm_100 (no 'a' features)
// ============================================================================

#define NUM_HEADS 6
#define DIM       192
#define NWIN      64
#define SCALE_F   0.17677669529663687f   // 32^-0.5
#define KSTEPS    12                     // 192 / 16

#define LDW   200     // padded row length (fp16); word stride 100 ≡ 4 mod 32
#define LDWU  100
#define LDM2  36      // mask row stride (half2 words): bank = lane -> conflict-free

// SMEM layout (bytes): 4 buffers of 64*200*2 = 25600
#define XB_OFF   0          // x staging; later mask-half2 (64*36*4=9216B) + table @+9216
#define QB_OFF   25600      // q, later O
#define KB_OFF   51200
#define VB_OFF   76800
#define SMEM_TOTAL 102400

// Weights in mma-B-fragment order: frag index ((t*12 + s)*32 + lane), uint4 each.
__device__ __align__(16) uint4 g_bq [12 * KSTEPS * 32];
__device__ __align__(16) uint4 g_bkv[24 * KSTEPS * 32];
__device__ __align__(16) uint4 g_bp [12 * KSTEPS * 32];

static __device__ __forceinline__ unsigned pack_half2(float a, float b) {
    __half2 h = __floats2half2_rn(a, b);
    return *(unsigned*)&h;
}

static __device__ __forceinline__ uint4 make_frag(const float* __restrict__ W,
                                                  int t, int s, int l) {
    int n  = t * 16 + (l >> 2);
    int k0 = s * 16 + (l & 3) * 2;
    const float* r0 = W + (size_t)n * DIM;
    const float* r1 = W + (size_t)(n + 8) * DIM;
    uint4 u;
    u.x = pack_half2(r0[k0],     r0[k0 + 1]);
    u.y = pack_half2(r0[k0 + 8], r0[k0 + 9]);
    u.z = pack_half2(r1[k0],     r1[k0 + 1]);
    u.w = pack_half2(r1[k0 + 8], r1[k0 + 9]);
    return u;
}

__global__ void prep_kernel(const float* __restrict__ qw,
                            const float* __restrict__ kvw,
                            const float* __restrict__ pw) {
    int i = blockIdx.x * blockDim.x + threadIdx.x;   // 18432 total
    if (i < 4608) {
        int t = i / 384, r = i % 384, s = r / 32, l = r % 32;
        g_bq[i] = make_frag(qw, t, s, l);
    } else if (i < 13824) {
        int j = i - 4608;
        int t = j / 384, r = j % 384, s = r / 32, l = r % 32;
        g_bkv[j] = make_frag(kvw, t, s, l);
    } else if (i < 18432) {
        int j = i - 13824;
        int t = j / 384, r = j % 384, s = r / 32, l = r % 32;
        g_bp[j] = make_frag(pw, t, s, l);
    }
}

static __device__ __forceinline__ unsigned sm_u32(const void* p) {
    return (unsigned)__cvta_generic_to_shared(p);
}

#define LDM_X4(R, ADDR) \
    asm volatile("ldmatrix.sync.aligned.m8n8.x4.shared.b16 {%0,%1,%2,%3}, [%4];" \
                 : "=r"((R)[0]), "=r"((R)[1]), "=r"((R)[2]), "=r"((R)[3]) : "r"(ADDR))
#define LDM_X2(R, ADDR) \
    asm volatile("ldmatrix.sync.aligned.m8n8.x2.shared.b16 {%0,%1}, [%2];" \
                 : "=r"((R)[0]), "=r"((R)[1]) : "r"(ADDR))
#define LDM_X2T(R, ADDR) \
    asm volatile("ldmatrix.sync.aligned.m8n8.x2.trans.shared.b16 {%0,%1}, [%2];" \
                 : "=r"((R)[0]), "=r"((R)[1]) : "r"(ADDR))
#define MMA_F16(D, A, B) \
    asm volatile("mma.sync.aligned.m16n8k16.row.col.f32.f16.f16.f32 " \
                 "{%0,%1,%2,%3},{%4,%5,%6,%7},{%8,%9},{%0,%1,%2,%3};" \
                 : "+f"((D)[0]), "+f"((D)[1]), "+f"((D)[2]), "+f"((D)[3]) \
                 : "r"((A)[0]), "r"((A)[1]), "r"((A)[2]), "r"((A)[3]), \
                   "r"((B)[0]), "r"((B)[1]))

// 32(M) x 32(N) x 192(K) warp GEMM: A fp16 in smem, B fragments from gmem.
static __device__ __forceinline__ void gemm32x32(unsigned a_u, int mrow0,
                                                 const uint4* __restrict__ bt0,
                                                 const uint4* __restrict__ bt1,
                                                 int lane, float acc[2][4][4]) {
#pragma unroll
    for (int mt = 0; mt < 2; mt++)
#pragma unroll
        for (int n8 = 0; n8 < 4; n8++)
#pragma unroll
            for (int r = 0; r < 4; r++) acc[mt][n8][r] = 0.f;

    const unsigned aAddr = a_u + (((mrow0 + (lane & 15)) * LDW + (lane >> 4) * 8) * 2);
    uint4 b0c = bt0[lane], b1c = bt1[lane];
#pragma unroll
    for (int s = 0; s < KSTEPS; s++) {
        uint4 b0n = (s + 1 < KSTEPS) ? bt0[(s + 1) * 32 + lane] : b0c;
        uint4 b1n = (s + 1 < KSTEPS) ? bt1[(s + 1) * 32 + lane] : b1c;
        unsigned B0[2] = { b0c.x, b0c.y };
        unsigned B1[2] = { b0c.z, b0c.w };
        unsigned B2[2] = { b1c.x, b1c.y };
        unsigned B3[2] = { b1c.z, b1c.w };
#pragma unroll
        for (int mt = 0; mt < 2; mt++) {
            unsigned A[4];
            LDM_X4(A, aAddr + (s * 16) * 2 + mt * (16 * LDW * 2));
            MMA_F16(acc[mt][0], A, B0);
            MMA_F16(acc[mt][1], A, B1);
            MMA_F16(acc[mt][2], A, B2);
            MMA_F16(acc[mt][3], A, B3);
        }
        b0c = b0n; b1c = b1n;
    }
}

__global__ void __launch_bounds__(384, 2)
wca_kernel(const float* __restrict__ x1, const float* __restrict__ x2,
           const float* __restrict__ mask,
           const float* __restrict__ q_b, const float* __restrict__ kv_b,
           const float* __restrict__ proj_b, const float* __restrict__ table,
           float* __restrict__ out) {
    extern __shared__ __align__(16) unsigned char smem[];
    __half* XB = (__half*)(smem + XB_OFF);
    __half* QB = (__half*)(smem + QB_OFF);
    __half* KB = (__half*)(smem + KB_OFF);
    __half* VB = (__half*)(smem + VB_OFF);
    unsigned* MH = (unsigned*)(smem + XB_OFF);      // mask half2, 64*36*4 = 9216B
    float*  TS = (float*)(smem + XB_OFF + 9216);    // head-major table: 6*225*4 = 5400B

    const int tid  = threadIdx.x;
    const int lane = tid & 31;
    const int wid  = tid >> 5;
    const int b    = blockIdx.x;                     // one window

    const unsigned xb_u = sm_u32(XB), qb_u = sm_u32(QB);
    const unsigned kb_u = sm_u32(KB), vb_u = sm_u32(VB);
    const int rq = lane >> 2;            // 0..7
    const int cq = (lane & 3) * 2;       // 0,2,4,6

    // GEMM warp tiling: 2 mi (32 rows) x 6 ni (32 cols)
    const int mi = wid & 1;
    const int ni = wid >> 1;             // 0..5
    const int mrow0 = mi * 32;

    // ---- load x1 (64 x 192 fp32 -> fp16 smem) ----
    {
        const float4* src = (const float4*)(x1 + (size_t)b * NWIN * DIM);
        unsigned* xbu = (unsigned*)XB;
#pragma unroll
        for (int i = tid; i < 64 * 48; i += 384) {
            int r = i / 48, c = i % 48;
            float4 v = src[i];
            *(uint2*)(xbu + r * LDWU + c * 2) =
                make_uint2(pack_half2(v.x, v.y), pack_half2(v.z, v.w));
        }
    }
    __syncthreads();

    // ======================= Q projection (1 round) =======================
    {
        float acc[2][4][4];
        gemm32x32(xb_u, mrow0, g_bq + (2 * ni) * (KSTEPS * 32),
                  g_bq + (2 * ni + 1) * (KSTEPS * 32), lane, acc);
        int colb = ni * 32;
#pragma unroll
        for (int mt = 0; mt < 2; mt++)
#pragma unroll
            for (int n8 = 0; n8 < 4; n8++) {
                int row = mrow0 + mt * 16 + rq;
                int col = colb + n8 * 8 + cq;
                float2 bb = *(const float2*)(q_b + col);
                *(unsigned*)(QB + row * LDW + col) =
                    pack_half2((acc[mt][n8][0] + bb.x) * SCALE_F,
                               (acc[mt][n8][1] + bb.y) * SCALE_F);
                *(unsigned*)(QB + (row + 8) * LDW + col) =
                    pack_half2((acc[mt][n8][2] + bb.x) * SCALE_F,
                               (acc[mt][n8][3] + bb.y) * SCALE_F);
            }
    }
    __syncthreads();   // XB (x1) fully consumed

    // ---- load x2 into XB ----
    {
        const float4* src = (const float4*)(x2 + (size_t)b * NWIN * DIM);
        unsigned* xbu = (unsigned*)XB;
#pragma unroll
        for (int i = tid; i < 64 * 48; i += 384) {
            int r = i / 48, c = i % 48;
            float4 v = src[i];
            *(uint2*)(xbu + r * LDWU + c * 2) =
                make_uint2(pack_half2(v.x, v.y), pack_half2(v.z, v.w));
        }
    }
    __syncthreads();

    // ======================= K / V projection (2 iterations) ===============
#pragma unroll
    for (int it = 0; it < 2; it++) {
        int t0 = it * 12 + 2 * ni;        // fragment tile pair
        float acc[2][4][4];
        gemm32x32(xb_u, mrow0, g_bkv + t0 * (KSTEPS * 32),
                  g_bkv + (t0 + 1) * (KSTEPS * 32), lane, acc);
        __half* OB = it ? VB : KB;
        int cgb  = it * 192 + ni * 32;    // global output channel base
        int colb = ni * 32;               // local column base in K/V buffer
#pragma unroll
        for (int mt = 0; mt < 2; mt++)
#pragma unroll
            for (int n8 = 0; n8 < 4; n8++) {
                int row = mrow0 + mt * 16 + rq;
                int c8  = n8 * 8 + cq;
                float2 bb = *(const float2*)(kv_b + cgb + c8);
                int col = colb + c8;
                *(unsigned*)(OB + row * LDW + col) =
                    pack_half2(acc[mt][n8][0] + bb.x, acc[mt][n8][1] + bb.y);
                *(unsigned*)(OB + (row + 8) * LDW + col) =
                    pack_half2(acc[mt][n8][2] + bb.x, acc[mt][n8][3] + bb.y);
            }
    }
    __syncthreads();   // XB (x2) fully consumed

    // ---- stage mask (fp32 -> half2, bank==lane layout) + head-major table ----
    {
        const float2* mw = (const float2*)(mask + (size_t)(b & 1023) * (NWIN * NWIN));
#pragma unroll
        for (int i = tid; i < 64 * 32; i += 384) {
            int n = i >> 5, j = i & 31;
            float2 v = mw[i];
            MH[n * LDM2 + j] = pack_half2(v.x, v.y);
        }
        for (int i = tid; i < 225 * 6; i += 384) {
            int h = i / 225, idx = i % 225;
            TS[i] = table[idx * 6 + h];      // transpose to head-major
        }
    }
    __syncthreads();

    // ======================= Attention =======================
    // 24 subtasks = 6 heads x 4 row-quarters (16 rows); 12 warps x 2 iterations.
#pragma unroll
    for (int it = 0; it < 2; it++) {
        int st = wid + it * 12;
        int h = st >> 2, q4 = st & 3;
        int nrow0 = q4 * 16;
        const float* TH = TS + h * 225;

        unsigned qa[2][4];
        {
            unsigned base = qb_u + (((nrow0 + (lane & 15)) * LDW) + h * 32 + ((lane >> 4) * 8)) * 2;
            LDM_X4(qa[0], base);
            LDM_X4(qa[1], base + 16 * 2);
        }

        // S = Q K^T  (16 x 64)
        float s[8][4];
#pragma unroll
        for (int nt = 0; nt < 8; nt++)
#pragma unroll
            for (int r = 0; r < 4; r++) s[nt][r] = 0.f;
        {
            unsigned kbase = kb_u + (((lane & 7) * LDW) + h * 32 + (((lane >> 3) & 1) * 8)) * 2;
#pragma unroll
            for (int nt = 0; nt < 8; nt++) {
                unsigned B0[2], B1[2];
                LDM_X2(B0, kbase + nt * 8 * LDW * 2);
                LDM_X2(B1, kbase + nt * 8 * LDW * 2 + 16 * 2);
                MMA_F16(s[nt], qa[0], B0);
                MMA_F16(s[nt], qa[1], B1);
            }
        }

        // + relative-position bias (head-major, conflict-free) + mask (bank==lane)
#pragma unroll
        for (int hi = 0; hi < 2; hi++) {
            int n  = nrow0 + hi * 8 + rq;
            int pr = n >> 3, pc = n & 7;
            int roff = (pr + 7) * 15 + (pc - cq + 7);
            int mb = n * LDM2 + (cq >> 1);
#pragma unroll
            for (int nt = 0; nt < 8; nt++) {
                int idx0 = roff - nt * 15;
                unsigned u = MH[mb + nt * 4];
                float2 mv = __half22float2(*(__half2*)&u);
                s[nt][hi * 2]     += TH[idx0] + mv.x;
                s[nt][hi * 2 + 1] += TH[idx0 - 1] + mv.y;
            }
        }

        // softmax over 64 cols (row spread across 4 lanes -> quad shuffles)
#pragma unroll
        for (int hi = 0; hi < 2; hi++) {
            float mx = -1e30f;
#pragma unroll
            for (int nt = 0; nt < 8; nt++)
                mx = fmaxf(mx, fmaxf(s[nt][hi * 2], s[nt][hi * 2 + 1]));
            mx = fmaxf(mx, __shfl_xor_sync(0xffffffffu, mx, 1));
            mx = fmaxf(mx, __shfl_xor_sync(0xffffffffu, mx, 2));
            float sum = 0.f;
#pragma unroll
            for (int nt = 0; nt < 8; nt++) {
                float p0 = __expf(s[nt][hi * 2]     - mx);
                float p1 = __expf(s[nt][hi * 2 + 1] - mx);
                s[nt][hi * 2] = p0; s[nt][hi * 2 + 1] = p1;
                sum += p0 + p1;
            }
            sum += __shfl_xor_sync(0xffffffffu, sum, 1);
            sum += __shfl_xor_sync(0xffffffffu, sum, 2);
            float inv = 1.f / sum;
#pragma unroll
            for (int nt = 0; nt < 8; nt++) {
                s[nt][hi * 2] *= inv; s[nt][hi * 2 + 1] *= inv;
            }
        }

        // pack P (accumulator layout == next mma A layout)
        unsigned pk[8][2];
#pragma unroll
        for (int nt = 0; nt < 8; nt++) {
            pk[nt][0] = pack_half2(s[nt][0], s[nt][1]);
            pk[nt][1] = pack_half2(s[nt][2], s[nt][3]);
        }

        // O = P V  (16 x 32)
        float o[4][4];
#pragma unroll
        for (int dt = 0; dt < 4; dt++)
#pragma unroll
            for (int r = 0; r < 4; r++) o[dt][r] = 0.f;
#pragma unroll
        for (int j = 0; j < 4; j++) {
            unsigned vb[4][2];
            unsigned vbase = vb_u + (((j * 16 + (lane & 15)) * LDW) + h * 32) * 2;
#pragma unroll
            for (int dt = 0; dt < 4; dt++) LDM_X2T(vb[dt], vbase + dt * 8 * 2);
            unsigned pa[4] = { pk[2 * j][0], pk[2 * j][1],
                               pk[2 * j + 1][0], pk[2 * j + 1][1] };
#pragma unroll
            for (int dt = 0; dt < 4; dt++) MMA_F16(o[dt], pa, vb[dt]);
        }

        // write O over this subtask's Q slice (half2 stores)
#pragma unroll
        for (int dt = 0; dt < 4; dt++) {
            int row = nrow0 + rq;
            int col = h * 32 + dt * 8 + cq;
            *(unsigned*)(QB + row * LDW + col)       = pack_half2(o[dt][0], o[dt][1]);
            *(unsigned*)(QB + (row + 8) * LDW + col) = pack_half2(o[dt][2], o[dt][3]);
        }
    }
    __syncthreads();   // all O visible before projection

    // ======================= Output projection (1 round) ==================
    {
        float acc[2][4][4];
        gemm32x32(qb_u, mrow0, g_bp + (2 * ni) * (KSTEPS * 32),
                  g_bp + (2 * ni + 1) * (KSTEPS * 32), lane, acc);
        int colb = ni * 32;
        float* ob = out + (size_t)b * NWIN * DIM;
#pragma unroll
        for (int mt = 0; mt < 2; mt++)
#pragma unroll
            for (int n8 = 0; n8 < 4; n8++) {
                int row = mrow0 + mt * 16 + rq;
                int col = colb + n8 * 8 + cq;
                float2 bb = *(const float2*)(proj_b + col);
                float2 r0 = make_float2(acc[mt][n8][0] + bb.x, acc[mt][n8][1] + bb.y);
                float2 r1 = make_float2(acc[mt][n8][2] + bb.x, acc[mt][n8][3] + bb.y);
                *(float2*)(ob + (size_t)row * DIM + col)       = r0;
                *(float2*)(ob + (size_t)(row + 8) * DIM + col) = r1;
            }
    }
}

extern "C" void kernel_launch(void* const* d_in, const int* in_sizes, int n_in,
                              void* d_out, int out_size) {
    const float* x1     = (const float*)d_in[0];
    const float* x2     = (const float*)d_in[1];
    const float* mask   = (const float*)d_in[2];
    const float* q_w    = (const float*)d_in[3];
    const float* q_b    = (const float*)d_in[4];
    const float* kv_w   = (const float*)d_in[5];
    const float* kv_b   = (const float*)d_in[6];
    const float* proj_w = (const float*)d_in[7];
    const float* proj_b = (const float*)d_in[8];
    const float* table  = (const float*)d_in[9];

    prep_kernel<<<72, 256>>>(q_w, kv_w, proj_w);

    cudaFuncSetAttribute(wca_kernel, cudaFuncAttributeMaxDynamicSharedMemorySize, SMEM_TOTAL);
    wca_kernel<<<8192, 384, SMEM_TOTAL>>>(x1, x2, mask, q_b, kv_b, proj_b, table,
                                          (float*)d_out);
}